// round 1
// baseline (speedup 1.0000x reference)
#include <cuda_runtime.h>

#define BSZ 2
#define SEQ 4096
#define NH 16
#define DP 64
#define DN 128
#define CS 64
#define NC 64
#define NPAIR (BSZ*NH)          // 32
#define NSLICE 4
#define PW (DP/NSLICE)          // 16
#define MAIN_CTAS (NPAIR*NSLICE) // 128
#define TPB 256

// ---------------- device scratch (module-scope: allowed) ----------------
__device__ float g_CB[(size_t)NC*NPAIR*CS*CS];   // 33.5 MB precomputed C·B^T
__device__ float g_err[2][NPAIR][NSLICE];        // double-buffered partial ||h_contrib||^2
__device__ unsigned g_arrive;
__device__ unsigned g_release;

__global__ void init_kernel() { g_arrive = 0u; g_release = 0u; }

// ---------------- pre-pass: CB[c,pair,i,j] = sum_n C[i,n] B[j,n] ----------------
__global__ void __launch_bounds__(TPB) cb_kernel(const float* __restrict__ Cm,
                                                 const float* __restrict__ Bm) {
    extern __shared__ float smem[];
    float* sC = smem;                // [64][129]
    float* sB = smem + CS * 129;     // [64][129]
    int tile = blockIdx.x;
    int c = tile >> 5;
    int pair = tile & 31;
    int b = pair >> 4, h = pair & 15;
    size_t base = ((size_t)((size_t)b * SEQ + (size_t)c * CS) * NH + h) * DN;
    const float* Cg = Cm + base;
    const float* Bg = Bm + base;
    const int gs = NH * DN;          // 2048 floats between consecutive s
    for (int idx = threadIdx.x; idx < CS * DN; idx += TPB) {
        int i = idx >> 7, n = idx & 127;
        sC[i * 129 + n] = Cg[(size_t)i * gs + n];
        sB[i * 129 + n] = Bg[(size_t)i * gs + n];
    }
    __syncthreads();
    int tx = threadIdx.x & 15, ty = threadIdx.x >> 4;
    int i0 = ty * 4, j0 = tx * 4;
    float acc[4][4];
#pragma unroll
    for (int a = 0; a < 4; a++)
#pragma unroll
        for (int e = 0; e < 4; e++) acc[a][e] = 0.f;
#pragma unroll 4
    for (int n = 0; n < DN; n++) {
        float cr[4], br[4];
#pragma unroll
        for (int a = 0; a < 4; a++) cr[a] = sC[(i0 + a) * 129 + n];
#pragma unroll
        for (int e = 0; e < 4; e++) br[e] = sB[(j0 + e) * 129 + n];
#pragma unroll
        for (int a = 0; a < 4; a++)
#pragma unroll
            for (int e = 0; e < 4; e++) acc[a][e] = fmaf(cr[a], br[e], acc[a][e]);
    }
    float* out = g_CB + (size_t)(c * NPAIR + pair) * CS * CS;
#pragma unroll
    for (int a = 0; a < 4; a++) {
        float4 v = make_float4(acc[a][0], acc[a][1], acc[a][2], acc[a][3]);
        *reinterpret_cast<float4*>(out + (i0 + a) * CS + j0) = v;
    }
}

// ---------------- persistent sequential kernel ----------------
__device__ __forceinline__ void grid_barrier(unsigned gen) {
    __syncthreads();
    if (threadIdx.x == 0) {
        __threadfence();
        unsigned a = atomicAdd(&g_arrive, 1u);
        unsigned target = (gen + 1u) * (unsigned)MAIN_CTAS;
        if (a == target - 1u) {
            __threadfence();
            atomicExch(&g_release, gen + 1u);
        } else {
            while (*(volatile unsigned*)&g_release <= gen) { __nanosleep(64); }
            __threadfence();
        }
    }
    __syncthreads();
}

__global__ void __launch_bounds__(TPB) ssd_main_kernel(
    const float* __restrict__ X, const float* __restrict__ A,
    const float* __restrict__ Bm, const float* __restrict__ Cm,
    const float* __restrict__ la, const float* __restrict__ lb,
    const float* __restrict__ ema0, float* __restrict__ Y) {
    extern __shared__ float smem[];
    float* sh   = smem;               // h state [128][16]         2048
    float* sC   = sh + DN * PW;       // C tile [64][129]          8256
    float* sB   = sC + CS * 129;      // B tile [64][128]          8192
    float* sM   = sB + CS * DN;       // L*CB  [64][65]            4160
    float* sX   = sM + CS * 65;       // X tile [64][16]           1024
    float* sXw  = sX + CS * PW;       // dte-weighted X            1024
    float* sAcs = sXw + CS * PW;      // 64
    float* sDfs = sAcs + CS;          // 64
    float* sInv = sDfs + CS;          // 64
    float* sDte = sInv + CS;          // 64
    float* sAraw = sDte + CS;         // 64
    float* sEma = sAraw + CS;         // 16
    float* sAB  = sEma + NH;          // 16
    float* sBet = sAB + NH;           // 16
    float* sDS  = sBet + NH;          // 1
    float* sRed = sDS + 1;            // 8

    const int tid = threadIdx.x;
    const int lane = tid & 31;
    const int wid = tid >> 5;
    const int pair = blockIdx.x >> 2;
    const int slice = blockIdx.x & 3;
    const int b = pair >> 4, h = pair & 15;
    const int p0 = slice * PW;

    // init state + per-head gate constants
    for (int i = tid; i < DN * PW; i += TPB) sh[i] = 0.f;
    if (tid < NH) {
        float v = fminf(fmaxf(la[tid], -3.32f), -0.015f);
        sAB[tid] = 1.f - exp2f(v);
        float w = fminf(fmaxf(lb[tid], -2.f), 2.f);
        sBet[tid] = exp2f(w);
        sEma[tid] = ema0[tid];
    }
    __syncthreads();

    unsigned gen = 0;
    for (int c = 0; c < NC; ++c) {
        if (c > 0) { grid_barrier(gen); gen++; }

        // stage raw A values for this chunk (warps 2,3 — doesn't collide with gate warp)
        if (tid >= 64 && tid < 128) {
            int t = tid - 64;
            sAraw[t] = A[((size_t)((size_t)b * SEQ + c * CS + t)) * NH + h];
        }

        // ---- gate: decay_scale + EMA update (redundant, bitwise identical per CTA) ----
        if (c == 0) {
            if (tid == 0) sDS[0] = 1.f;
        } else if (wid == 0) {
            int hh = lane & 15;
            const float* eb = &g_err[(c - 1) & 1][lane][0];
            float e = (((eb[0] + eb[1]) + eb[2]) + eb[3]) * (1.f / (float)(DN * DP));
            float e0 = __shfl_sync(0xffffffffu, e, hh);
            float e1 = __shfl_sync(0xffffffffu, e, hh + 16);
            float emn = 0.99f * sEma[hh] + 0.01f * (0.5f * (e0 + e1));
            __syncwarp();
            if (lane < 16) sEma[hh] = emn;
            __syncwarp();
            float nrm = e / (emn + 1e-6f);
            float boost = fmaxf(tanhf(sBet[hh] * nrm), 0.f);
            float ab = sAB[hh];
            float alpha = fminf(fmaxf(ab + (1.f - ab) * boost, 0.01f), 0.999f);
            float oma = 1.f - alpha;
#pragma unroll
            for (int o = 16; o; o >>= 1) oma += __shfl_xor_sync(0xffffffffu, oma, o);
            if (lane == 0) sDS[0] = oma * (1.f / 32.f);
        }
        __syncthreads();

        // ---- cumsum(A * ds) and exponentials ----
        if (tid == 0) {
            float dsv = sDS[0];
            float run = 0.f;
#pragma unroll
            for (int i = 0; i < CS; i++) { run = fmaf(sAraw[i], dsv, run); sAcs[i] = run; }
        }
        __syncthreads();
        {
            float a63 = sAcs[CS - 1];
            if (tid < CS) {
                float a = sAcs[tid];
                sDfs[tid] = expf(a);          // decay_from_start
                sInv[tid] = expf(-a);
                sDte[tid] = expf(a63 - a);    // decay_to_end
            }
        }
        __syncthreads();

        // ---- tile loads ----
        const size_t rowbase = ((size_t)((size_t)b * SEQ + c * CS) * NH + h);
        const float* Cg = Cm + rowbase * DN;
        const float* Xg = X + rowbase * DP + p0;
        const int gsCB = NH * DN;  // 2048 floats
        const int gsX = NH * DP;   // 1024 floats
        for (int idx = tid; idx < CS * DN; idx += TPB) {
            int i = idx >> 7, n = idx & 127;
            sC[i * 129 + n] = Cg[(size_t)i * gsCB + n];
        }
        {
            const float4* Bg4 = (const float4*)(Bm + rowbase * DN);
            float4* sB4 = (float4*)sB;
            for (int idx = tid; idx < CS * DN / 4; idx += TPB) {
                int i = idx >> 5, n4 = idx & 31;
                sB4[i * 32 + n4] = Bg4[(size_t)i * (gsCB / 4) + n4];
            }
        }
        {
            const float4* Xg4 = (const float4*)Xg;
            float4* sX4 = (float4*)sX;
            if (tid < CS * PW / 4) {
                int i = tid >> 2, p4 = tid & 3;
                sX4[i * 4 + p4] = Xg4[(size_t)i * (gsX / 4) + p4];
            }
        }
        {
            const float* cbg = g_CB + (size_t)(c * NPAIR + pair) * CS * CS;
            for (int idx = tid; idx < CS * CS; idx += TPB) {
                int i = idx >> 6, j = idx & 63;
                float v = (i >= j) ? cbg[idx] * sDfs[i] * sInv[j] : 0.f;
                sM[i * 65 + j] = v;
            }
        }
        __syncthreads();
        for (int k = tid; k < CS * PW; k += TPB) sXw[k] = sDte[k >> 4] * sX[k];
        __syncthreads();

        // ---- Y = (L*CB) @ X + diag(dfs) C @ h ----
        {
            int yi = tid & 63, pg = tid >> 6;
            float4 acc = make_float4(0.f, 0.f, 0.f, 0.f);
            const float* mrow = sM + yi * 65;
            const float* xcol = sX + pg * 4;
#pragma unroll 4
            for (int j = 0; j < CS; j++) {
                float m = mrow[j];
                float4 x = *(const float4*)(xcol + j * PW);
                acc.x = fmaf(m, x.x, acc.x);
                acc.y = fmaf(m, x.y, acc.y);
                acc.z = fmaf(m, x.z, acc.z);
                acc.w = fmaf(m, x.w, acc.w);
            }
            float4 a2 = make_float4(0.f, 0.f, 0.f, 0.f);
            const float* crow = sC + yi * 129;
            const float* hcol = sh + pg * 4;
#pragma unroll 4
            for (int n = 0; n < DN; n++) {
                float cv = crow[n];
                float4 hv = *(const float4*)(hcol + n * PW);
                a2.x = fmaf(cv, hv.x, a2.x);
                a2.y = fmaf(cv, hv.y, a2.y);
                a2.z = fmaf(cv, hv.z, a2.z);
                a2.w = fmaf(cv, hv.w, a2.w);
            }
            float d = sDfs[yi];
            acc.x = fmaf(d, a2.x, acc.x);
            acc.y = fmaf(d, a2.y, acc.y);
            acc.z = fmaf(d, a2.z, acc.z);
            acc.w = fmaf(d, a2.w, acc.w);
            float* yo = Y + (rowbase + (size_t)yi * NH) * DP + p0 + pg * 4;
            *(float4*)yo = acc;
        }
        __syncthreads();  // all reads of h done before overwrite

        // ---- h = dt*h + B^T @ (dte*X);  err_part = ||contrib||^2 ----
        float esum;
        {
            int n0 = tid & 63, pg = tid >> 6;
            float4 c1 = make_float4(0.f, 0.f, 0.f, 0.f);
            float4 c2 = make_float4(0.f, 0.f, 0.f, 0.f);
            const float* xw = sXw + pg * 4;
#pragma unroll 4
            for (int t = 0; t < CS; t++) {
                float b1 = sB[t * DN + n0];
                float b2 = sB[t * DN + n0 + 64];
                float4 w = *(const float4*)(xw + t * PW);
                c1.x = fmaf(b1, w.x, c1.x); c1.y = fmaf(b1, w.y, c1.y);
                c1.z = fmaf(b1, w.z, c1.z); c1.w = fmaf(b1, w.w, c1.w);
                c2.x = fmaf(b2, w.x, c2.x); c2.y = fmaf(b2, w.y, c2.y);
                c2.z = fmaf(b2, w.z, c2.z); c2.w = fmaf(b2, w.w, c2.w);
            }
            float dt = sDfs[CS - 1];
            float* h1p = sh + n0 * PW + pg * 4;
            float* h2p = sh + (n0 + 64) * PW + pg * 4;
            float4 h1 = *(float4*)h1p, h2 = *(float4*)h2p;
            h1.x = fmaf(dt, h1.x, c1.x); h1.y = fmaf(dt, h1.y, c1.y);
            h1.z = fmaf(dt, h1.z, c1.z); h1.w = fmaf(dt, h1.w, c1.w);
            h2.x = fmaf(dt, h2.x, c2.x); h2.y = fmaf(dt, h2.y, c2.y);
            h2.z = fmaf(dt, h2.z, c2.z); h2.w = fmaf(dt, h2.w, c2.w);
            *(float4*)h1p = h1; *(float4*)h2p = h2;
            esum = c1.x * c1.x + c1.y * c1.y + c1.z * c1.z + c1.w * c1.w
                 + c2.x * c2.x + c2.y * c2.y + c2.z * c2.z + c2.w * c2.w;
        }
#pragma unroll
        for (int o = 16; o; o >>= 1) esum += __shfl_xor_sync(0xffffffffu, esum, o);
        if (lane == 0) sRed[wid] = esum;
        __syncthreads();
        if (tid == 0) {
            float tot = 0.f;
#pragma unroll
            for (int w = 0; w < 8; w++) tot += sRed[w];
            g_err[c & 1][pair][slice] = tot;
        }
        // next iteration's grid_barrier provides the fence + syncthreads
    }
}

// ---------------- launch ----------------
extern "C" void kernel_launch(void* const* d_in, const int* in_sizes, int n_in,
                              void* d_out, int out_size) {
    const float* X   = (const float*)d_in[0];
    const float* A   = (const float*)d_in[1];
    const float* Bm  = (const float*)d_in[2];
    const float* Cm  = (const float*)d_in[3];
    const float* la  = (const float*)d_in[4];
    const float* lb  = (const float*)d_in[5];
    const float* em  = (const float*)d_in[6];
    float* Y = (float*)d_out;

    static const int cb_smem = 2 * CS * 129 * sizeof(float);          // 66048 B
    static const int main_smem = (DN * PW + CS * 129 + CS * DN + CS * 65 +
                                  2 * CS * PW + 5 * CS + 3 * NH + 1 + 8) * sizeof(float);
    cudaFuncSetAttribute(cb_kernel, cudaFuncAttributeMaxDynamicSharedMemorySize, cb_smem);
    cudaFuncSetAttribute(ssd_main_kernel, cudaFuncAttributeMaxDynamicSharedMemorySize, main_smem);

    init_kernel<<<1, 1>>>();
    cb_kernel<<<NC * NPAIR, TPB, cb_smem>>>(Cm, Bm);
    ssd_main_kernel<<<MAIN_CTAS, TPB, main_smem>>>(X, A, Bm, Cm, la, lb, em, Y);
}

// round 2
// speedup vs baseline: 2.3233x; 2.3233x over previous
#include <cuda_runtime.h>

#define BSZ 2
#define SEQ 4096
#define NH 16
#define DP 64
#define DN 128
#define CS 64
#define NC 64
#define NPAIR 32
#define NSLICE 4
#define PW 16
#define MAIN_CTAS 128
#define TPB 256

// ---------------- device scratch ----------------
__device__ float g_CB[(size_t)NC * NPAIR * CS * CS];  // 33.5 MB precomputed C·B^T
__device__ float g_err[2][NPAIR][NSLICE];
__device__ unsigned g_arrive;
__device__ unsigned g_release;

// ---------------- smem layout (floats) for main kernel ----------------
#define OFF_SH   0        // h state [128][16]            2048
#define OFF_SM   2048     // L*CB [64][65]                4160
#define OFF_SXW  6208     // dte-weighted X [64][16]      1024
#define OFF_SP   7232     // prefix sums of A             64
#define OFF_DFS  7296     // 64
#define OFF_INV  7360     // 64
#define OFF_DTE  7424     // 64
#define OFF_EMA  7488     // 16
#define OFF_AB   7504     // 16
#define OFF_BET  7520     // 16
#define OFF_DS   7536     // 1
#define OFF_RED  7540     // 8
#define OFF_BUF0 7552
#define B_C  0            // C tile [64][129]  8256
#define B_B  8256         // B tile [64][128]  8192
#define B_CB 16448        // raw CB [64][64]   4096
#define B_X  20544        // X tile [64][16]   1024
#define B_A  21568        // A raw             64
#define BUFSZ 21632
#define OFF_BUF1 (OFF_BUF0 + BUFSZ)
#define SMEM_FLOATS (OFF_BUF1 + BUFSZ)   // 50816 floats = 203264 B

// ---------------- cp.async helpers ----------------
__device__ __forceinline__ void cpa16(float* s, const float* g) {
    unsigned a = (unsigned)__cvta_generic_to_shared(s);
    asm volatile("cp.async.cg.shared.global [%0], [%1], 16;\n" :: "r"(a), "l"(g));
}
__device__ __forceinline__ void cpa4(float* s, const float* g) {
    unsigned a = (unsigned)__cvta_generic_to_shared(s);
    asm volatile("cp.async.ca.shared.global [%0], [%1], 4;\n" :: "r"(a), "l"(g));
}
#define CP_COMMIT() asm volatile("cp.async.commit_group;\n" ::: "memory")
#define CP_WAIT1()  asm volatile("cp.async.wait_group 1;\n" ::: "memory")
#define CP_WAIT0()  asm volatile("cp.async.wait_group 0;\n" ::: "memory")

// ---------------- pre-pass: CB[c,pair,i,j] = sum_n C[i,n] B[j,n] ----------------
__global__ void __launch_bounds__(TPB) cb_kernel(const float* __restrict__ Cm,
                                                 const float* __restrict__ Bm) {
    if (blockIdx.x == 0 && threadIdx.x == 0) { g_arrive = 0u; g_release = 0u; }
    extern __shared__ float smem[];
    float* sC = smem;                // [64][129]
    float* sB = smem + CS * 129;     // [64][129]
    int tile = blockIdx.x;
    int c = tile >> 5;
    int pair = tile & 31;
    int b = pair >> 4, h = pair & 15;
    size_t base = ((size_t)((size_t)b * SEQ + (size_t)c * CS) * NH + h) * DN;
    const float* Cg = Cm + base;
    const float* Bg = Bm + base;
    const int gs = NH * DN;
    for (int idx = threadIdx.x; idx < CS * DN; idx += TPB) {
        int i = idx >> 7, n = idx & 127;
        sC[i * 129 + n] = Cg[(size_t)i * gs + n];
        sB[i * 129 + n] = Bg[(size_t)i * gs + n];
    }
    __syncthreads();
    int tx = threadIdx.x & 15, ty = threadIdx.x >> 4;
    int i0 = ty * 4, j0 = tx * 4;
    float acc[4][4];
#pragma unroll
    for (int a = 0; a < 4; a++)
#pragma unroll
        for (int e = 0; e < 4; e++) acc[a][e] = 0.f;
#pragma unroll 4
    for (int n = 0; n < DN; n++) {
        float cr[4], br[4];
#pragma unroll
        for (int a = 0; a < 4; a++) cr[a] = sC[(i0 + a) * 129 + n];
#pragma unroll
        for (int e = 0; e < 4; e++) br[e] = sB[(j0 + e) * 129 + n];
#pragma unroll
        for (int a = 0; a < 4; a++)
#pragma unroll
            for (int e = 0; e < 4; e++) acc[a][e] = fmaf(cr[a], br[e], acc[a][e]);
    }
    float* out = g_CB + (size_t)(c * NPAIR + pair) * CS * CS;
#pragma unroll
    for (int a = 0; a < 4; a++) {
        float4 v = make_float4(acc[a][0], acc[a][1], acc[a][2], acc[a][3]);
        *reinterpret_cast<float4*>(out + (i0 + a) * CS + j0) = v;
    }
}

// ---------------- prefetch chunk tiles via cp.async ----------------
__device__ __forceinline__ void prefetch_chunk(
    int cc, float* buf, int b, int h, int pair, int p0, int tid,
    const float* __restrict__ X, const float* __restrict__ A,
    const float* __restrict__ Bm, const float* __restrict__ Cm) {
    size_t rowbase = ((size_t)((size_t)b * SEQ + (size_t)cc * CS) * NH + h);
    const float* Cg = Cm + rowbase * DN;
    const float* Bg = Bm + rowbase * DN;
    const float* Xg = X + rowbase * DP + p0;
    const float* CBg = g_CB + (size_t)(cc * NPAIR + pair) * CS * CS;
    // C tile: 4B copies into 129-padded rows (odd pad => conflict-free column reads)
    for (int idx = tid; idx < CS * DN; idx += TPB) {
        int i = idx >> 7, n = idx & 127;
        cpa4(buf + B_C + i * 129 + n, Cg + (size_t)i * (NH * DN) + n);
    }
    // B tile: 16B, unpadded (row-major reads are conflict-free)
    for (int idx = tid; idx < CS * DN / 4; idx += TPB) {
        int i = idx >> 5, n4 = idx & 31;
        cpa16(buf + B_B + i * DN + n4 * 4, Bg + (size_t)i * (NH * DN) + n4 * 4);
    }
    // raw CB: 16B contiguous
    for (int idx = tid; idx < CS * CS / 4; idx += TPB)
        cpa16(buf + B_CB + idx * 4, CBg + idx * 4);
    // X slice: 16B
    if (tid < CS * PW / 4) {
        int i = tid >> 2, p4 = tid & 3;
        cpa16(buf + B_X + i * PW + p4 * 4, Xg + (size_t)i * (NH * DP) + p4 * 4);
    }
    // A raw
    if (tid < CS)
        cpa4(buf + B_A + tid, A + ((size_t)((size_t)b * SEQ + cc * CS + tid)) * NH + h);
}

// ---------------- persistent sequential kernel ----------------
__global__ void __launch_bounds__(TPB, 1) ssd_main_kernel(
    const float* __restrict__ X, const float* __restrict__ A,
    const float* __restrict__ Bm, const float* __restrict__ Cm,
    const float* __restrict__ la, const float* __restrict__ lb,
    const float* __restrict__ ema0, float* __restrict__ Y) {
    extern __shared__ float smem[];
    const int tid = threadIdx.x;
    const int lane = tid & 31;
    const int wid = tid >> 5;
    const int pair = blockIdx.x >> 2;
    const int slice = blockIdx.x & 3;
    const int b = pair >> 4, h = pair & 15;
    const int p0 = slice * PW;
    const int yi = tid & 63;   // row / state-n index
    const int pg = tid >> 6;   // which 4-wide p group

    float* sh  = smem + OFF_SH;
    float* sM  = smem + OFF_SM;
    float* sXw = smem + OFF_SXW;
    float* sP  = smem + OFF_SP;
    float* sDfs = smem + OFF_DFS;
    float* sInv = smem + OFF_INV;
    float* sDte = smem + OFF_DTE;
    float* sEma = smem + OFF_EMA;
    float* sAB  = smem + OFF_AB;
    float* sBet = smem + OFF_BET;
    float* sDS  = smem + OFF_DS;
    float* sRed = smem + OFF_RED;

    // init state + per-head gate constants
    for (int i = tid; i < DN * PW; i += TPB) sh[i] = 0.f;
    if (tid < NH) {
        float v = fminf(fmaxf(la[tid], -3.32f), -0.015f);
        sAB[tid] = 1.f - exp2f(v);
        float w = fminf(fmaxf(lb[tid], -2.f), 2.f);
        sBet[tid] = exp2f(w);
        sEma[tid] = ema0[tid];
    }
    // prefetch chunk 0
    prefetch_chunk(0, smem + OFF_BUF0, b, h, pair, p0, tid, X, A, Bm, Cm);
    CP_COMMIT();
    __syncthreads();

    for (int c = 0; c < NC; ++c) {
        float* cur = smem + (((c & 1) == 0) ? OFF_BUF0 : OFF_BUF1);
        float* nxt = smem + (((c & 1) == 0) ? OFF_BUF1 : OFF_BUF0);

        // kick prefetch of next chunk, then wait for this chunk's tiles
        if (c + 1 < NC) {
            prefetch_chunk(c + 1, nxt, b, h, pair, p0, tid, X, A, Bm, Cm);
            CP_COMMIT();
            CP_WAIT1();
        } else {
            CP_WAIT0();
        }
        __syncthreads();

        // ds-independent prefix sums of raw A (off the gated critical path)
        if (tid == 0) {
            const float* sA = cur + B_A;
            float run = 0.f;
#pragma unroll
            for (int i = 0; i < CS; i++) { run += sA[i]; sP[i] = run; }
        }

        // ds-independent Y2 = C @ h_prev (overlaps the barrier wait)
        float4 y2 = make_float4(0.f, 0.f, 0.f, 0.f);
        if (c > 0) {
            const float* crow = cur + B_C + yi * 129;
            const float* hcol = sh + pg * 4;
#pragma unroll 8
            for (int n = 0; n < DN; n++) {
                float cv = crow[n];
                float4 hv = *(const float4*)(hcol + n * PW);
                y2.x = fmaf(cv, hv.x, y2.x);
                y2.y = fmaf(cv, hv.y, y2.y);
                y2.z = fmaf(cv, hv.z, y2.z);
                y2.w = fmaf(cv, hv.w, y2.w);
            }
        }

        // ---- wait for previous chunk's err, then gate ----
        if (c > 0) {
            if (tid == 0) {
                while (*(volatile unsigned*)&g_release < (unsigned)c) { }
                __threadfence();
            }
            __syncthreads();
            if (wid == 0) {
                int hh = lane & 15;
                float4 ev = __ldcg((const float4*)&g_err[(c - 1) & 1][lane][0]);
                float e = ((ev.x + ev.y) + (ev.z + ev.w)) * (1.f / (float)(DN * DP));
                float e0 = __shfl_sync(0xffffffffu, e, hh);
                float e1 = __shfl_sync(0xffffffffu, e, hh + 16);
                float emn = 0.99f * sEma[hh] + 0.01f * (0.5f * (e0 + e1));
                __syncwarp();
                if (lane < 16) sEma[hh] = emn;
                __syncwarp();
                float nrm = e / (emn + 1e-6f);
                float boost = fmaxf(tanhf(sBet[hh] * nrm), 0.f);
                float ab = sAB[hh];
                float alpha = fminf(fmaxf(ab + (1.f - ab) * boost, 0.01f), 0.999f);
                float oma = 1.f - alpha;
#pragma unroll
                for (int o = 16; o; o >>= 1) oma += __shfl_xor_sync(0xffffffffu, oma, o);
                if (lane == 0) sDS[0] = oma * (1.f / 32.f);
            }
        } else {
            if (tid == 0) sDS[0] = 1.f;
        }
        __syncthreads();

        // ---- decays ----
        {
            float dsv = sDS[0];
            if (tid < CS) {
                float a = dsv * sP[tid];
                float aT = dsv * sP[CS - 1];
                sDfs[tid] = __expf(a);
                sInv[tid] = __expf(-a);
                sDte[tid] = __expf(aT - a);
            }
        }
        __syncthreads();
        {
            const float* sX = cur + B_X;
            for (int k = tid; k < CS * PW; k += TPB) sXw[k] = sDte[k >> 4] * sX[k];
        }
        __syncthreads();

        // ---- h update (critical path): h = dt*h + B^T @ (dte*X); err part ----
        float esum;
        {
            const float* sB = cur + B_B;
            const float* xw = sXw + pg * 4;
            float4 c1 = make_float4(0.f, 0.f, 0.f, 0.f);
            float4 c2 = make_float4(0.f, 0.f, 0.f, 0.f);
#pragma unroll 4
            for (int t = 0; t < CS; t++) {
                float b1 = sB[t * DN + yi];
                float b2 = sB[t * DN + yi + 64];
                float4 w = *(const float4*)(xw + t * PW);
                c1.x = fmaf(b1, w.x, c1.x); c1.y = fmaf(b1, w.y, c1.y);
                c1.z = fmaf(b1, w.z, c1.z); c1.w = fmaf(b1, w.w, c1.w);
                c2.x = fmaf(b2, w.x, c2.x); c2.y = fmaf(b2, w.y, c2.y);
                c2.z = fmaf(b2, w.z, c2.z); c2.w = fmaf(b2, w.w, c2.w);
            }
            float dt = sDfs[CS - 1];
            float* h1p = sh + yi * PW + pg * 4;
            float* h2p = sh + (yi + 64) * PW + pg * 4;
            float4 h1 = *(float4*)h1p, h2 = *(float4*)h2p;
            h1.x = fmaf(dt, h1.x, c1.x); h1.y = fmaf(dt, h1.y, c1.y);
            h1.z = fmaf(dt, h1.z, c1.z); h1.w = fmaf(dt, h1.w, c1.w);
            h2.x = fmaf(dt, h2.x, c2.x); h2.y = fmaf(dt, h2.y, c2.y);
            h2.z = fmaf(dt, h2.z, c2.z); h2.w = fmaf(dt, h2.w, c2.w);
            *(float4*)h1p = h1; *(float4*)h2p = h2;
            esum = c1.x * c1.x + c1.y * c1.y + c1.z * c1.z + c1.w * c1.w
                 + c2.x * c2.x + c2.y * c2.y + c2.z * c2.z + c2.w * c2.w;
        }
#pragma unroll
        for (int o = 16; o; o >>= 1) esum += __shfl_xor_sync(0xffffffffu, esum, o);
        if (lane == 0) sRed[wid] = esum;
        __syncthreads();

        // ---- publish err + EARLY arrive (release happens asap) ----
        if (tid == 0) {
            float tot = 0.f;
#pragma unroll
            for (int w = 0; w < 8; w++) tot += sRed[w];
            g_err[c & 1][pair][slice] = tot;
            __threadfence();
            unsigned a = atomicAdd(&g_arrive, 1u);
            if (a == (unsigned)(c + 1) * (unsigned)MAIN_CTAS - 1u)
                atomicExch(&g_release, (unsigned)(c + 1));
        }

        // ---- shadow work: build masked L*CB, then Y = sM@X + dfs*Y2 ----
        {
            const float* sCB = cur + B_CB;
            for (int idx = tid; idx < CS * CS; idx += TPB) {
                int i = idx >> 6, j = idx & 63;
                float v = (i >= j) ? sCB[idx] * sDfs[i] * sInv[j] : 0.f;
                sM[i * 65 + j] = v;
            }
        }
        __syncthreads();
        {
            const float* mrow = sM + yi * 65;
            const float* xcol = cur + B_X + pg * 4;
            float4 acc = make_float4(0.f, 0.f, 0.f, 0.f);
#pragma unroll 8
            for (int j = 0; j < CS; j++) {
                float m = mrow[j];
                float4 x = *(const float4*)(xcol + j * PW);
                acc.x = fmaf(m, x.x, acc.x);
                acc.y = fmaf(m, x.y, acc.y);
                acc.z = fmaf(m, x.z, acc.z);
                acc.w = fmaf(m, x.w, acc.w);
            }
            float d = sDfs[yi];
            acc.x = fmaf(d, y2.x, acc.x);
            acc.y = fmaf(d, y2.y, acc.y);
            acc.z = fmaf(d, y2.z, acc.z);
            acc.w = fmaf(d, y2.w, acc.w);
            size_t rowbase = ((size_t)((size_t)b * SEQ + (size_t)c * CS) * NH + h);
            float* yo = Y + (rowbase + (size_t)yi * NH) * DP + p0 + pg * 4;
            *(float4*)yo = acc;
        }
        __syncthreads();  // protect cur buf (reused as prefetch target next iter)
    }
}

// ---------------- launch ----------------
extern "C" void kernel_launch(void* const* d_in, const int* in_sizes, int n_in,
                              void* d_out, int out_size) {
    const float* X  = (const float*)d_in[0];
    const float* A  = (const float*)d_in[1];
    const float* Bm = (const float*)d_in[2];
    const float* Cm = (const float*)d_in[3];
    const float* la = (const float*)d_in[4];
    const float* lb = (const float*)d_in[5];
    const float* em = (const float*)d_in[6];
    float* Y = (float*)d_out;

    const int cb_smem = 2 * CS * 129 * sizeof(float);
    const int main_smem = SMEM_FLOATS * sizeof(float);
    cudaFuncSetAttribute(cb_kernel, cudaFuncAttributeMaxDynamicSharedMemorySize, cb_smem);
    cudaFuncSetAttribute(ssd_main_kernel, cudaFuncAttributeMaxDynamicSharedMemorySize, main_smem);

    cb_kernel<<<NC * NPAIR, TPB, cb_smem>>>(Cm, Bm);
    ssd_main_kernel<<<MAIN_CTAS, TPB, main_smem>>>(X, A, Bm, Cm, la, lb, em, Y);
}

// round 3
// speedup vs baseline: 2.4122x; 1.0383x over previous
#include <cuda_runtime.h>

#define BSZ 2
#define SEQ 4096
#define NH 16
#define DP 64
#define DN 128
#define CS 64
#define NC 64
#define NPAIR 32
#define NSLICE 4
#define PW 16
#define MAIN_CTAS 128
#define MTPB 512
#define CTPB 256

// ---------------- device scratch ----------------
__device__ float g_CB[(size_t)NC * NPAIR * CS * CS];
__device__ float g_err[2][NPAIR][NSLICE];
__device__ unsigned g_arrive;
__device__ unsigned g_release;

// ---------------- smem layout (floats) for main kernel ----------------
#define OFF_SH   0        // h state [128][16]        2048
#define OFF_SM   2048     // L*CB [64][65]            4160
#define OFF_SXW  6208     // dte*X [64][16] / sPart   1024
#define OFF_SP   7232     // prefix sums of A         64
#define OFF_DFS  7296     // 64
#define OFF_EMA  7360     // 16
#define OFF_AB   7376     // 16
#define OFF_BET  7392     // 16
#define OFF_DS   7408     // 1
#define OFF_RED  7412     // 16
#define OFF_BUF0 7428     // pad to 16B boundary below
#define OFF_BUF0A 7432
#define B_C  0            // C tile [64][128] swizzled  8192
#define B_B  8192         // B tile [64][128]           8192
#define B_CB 16384        // raw CB [64][64]            4096
#define B_X  20480        // X slice [64][16]           1024
#define B_A  21504        // A raw                      64
#define BUFSZ 21568
#define OFF_BUF1 (OFF_BUF0A + BUFSZ)
#define SMEM_FLOATS (OFF_BUF1 + BUFSZ)   // 50568 floats = 202272 B

// ---------------- cp.async helpers ----------------
__device__ __forceinline__ void cpa16(float* s, const float* g) {
    unsigned a = (unsigned)__cvta_generic_to_shared(s);
    asm volatile("cp.async.cg.shared.global [%0], [%1], 16;\n" :: "r"(a), "l"(g));
}
__device__ __forceinline__ void cpa4(float* s, const float* g) {
    unsigned a = (unsigned)__cvta_generic_to_shared(s);
    asm volatile("cp.async.ca.shared.global [%0], [%1], 4;\n" :: "r"(a), "l"(g));
}
#define CP_COMMIT() asm volatile("cp.async.commit_group;\n" ::: "memory")
#define CP_WAIT1()  asm volatile("cp.async.wait_group 1;\n" ::: "memory")
#define CP_WAIT0()  asm volatile("cp.async.wait_group 0;\n" ::: "memory")

// ---------------- pre-pass: lower-triangle CB tiles only ----------------
__global__ void __launch_bounds__(CTPB) cb_kernel(const float* __restrict__ Cm,
                                                  const float* __restrict__ Bm) {
    if (blockIdx.x == 0 && threadIdx.x == 0) { g_arrive = 0u; g_release = 0u; }
    extern __shared__ float smem[];
    float* sC = smem;                // [64][129]
    float* sBt = smem + CS * 129;    // [64][129]
    int tile = blockIdx.x;
    int c = tile >> 5;
    int pair = tile & 31;
    int b = pair >> 4, h = pair & 15;
    size_t base = ((size_t)((size_t)b * SEQ + (size_t)c * CS) * NH + h) * DN;
    const float* Cg = Cm + base;
    const float* Bg = Bm + base;
    const int gs = NH * DN;
    for (int idx = threadIdx.x; idx < CS * DN; idx += CTPB) {
        int i = idx >> 7, n = idx & 127;
        sC[i * 129 + n] = Cg[(size_t)i * gs + n];
        sBt[i * 129 + n] = Bg[(size_t)i * gs + n];
    }
    __syncthreads();
    int t = threadIdx.x;
    if (t < 136) {  // 136 lower-triangle 4x4 tiles of the 16x16 tile grid
        int ti = (int)((sqrtf(8.f * (float)t + 1.f) - 1.f) * 0.5f);
        while ((ti + 1) * (ti + 2) / 2 <= t) ti++;
        while (ti * (ti + 1) / 2 > t) ti--;
        int tj = t - ti * (ti + 1) / 2;
        int i0 = ti * 4, j0 = tj * 4;
        float acc[4][4];
#pragma unroll
        for (int a = 0; a < 4; a++)
#pragma unroll
            for (int e = 0; e < 4; e++) acc[a][e] = 0.f;
#pragma unroll 4
        for (int n = 0; n < DN; n++) {
            float cr[4], br[4];
#pragma unroll
            for (int a = 0; a < 4; a++) cr[a] = sC[(i0 + a) * 129 + n];
#pragma unroll
            for (int e = 0; e < 4; e++) br[e] = sBt[(j0 + e) * 129 + n];
#pragma unroll
            for (int a = 0; a < 4; a++)
#pragma unroll
                for (int e = 0; e < 4; e++) acc[a][e] = fmaf(cr[a], br[e], acc[a][e]);
        }
        float* out = g_CB + (size_t)(c * NPAIR + pair) * CS * CS;
#pragma unroll
        for (int a = 0; a < 4; a++) {
            float4 v = make_float4(acc[a][0], acc[a][1], acc[a][2], acc[a][3]);
            *reinterpret_cast<float4*>(out + (i0 + a) * CS + j0) = v;
        }
    }
}

// ---------------- prefetch chunk tiles via cp.async (512 threads) ----------------
__device__ __forceinline__ void prefetch_chunk(
    int cc, float* buf, int b, int h, int pair, int p0, int tid,
    const float* __restrict__ X, const float* __restrict__ A,
    const float* __restrict__ Bm, const float* __restrict__ Cm) {
    size_t rowbase = ((size_t)((size_t)b * SEQ + (size_t)cc * CS) * NH + h);
    const float* Cg = Cm + rowbase * DN;
    const float* Bg = Bm + rowbase * DN;
    const float* Xg = X + rowbase * DP + p0;
    const float* CBg = g_CB + (size_t)(cc * NPAIR + pair) * CS * CS;
    // C tile: 16B groups, XOR-swizzled within row for conflict-free column reads
#pragma unroll
    for (int idx = tid; idx < CS * DN / 4; idx += MTPB) {
        int i = idx >> 5, n4 = idx & 31;
        cpa16(buf + B_C + i * DN + ((n4 ^ (i & 31)) << 2),
              Cg + (size_t)i * (NH * DN) + n4 * 4);
    }
    // B tile: 16B, row-major
#pragma unroll
    for (int idx = tid; idx < CS * DN / 4; idx += MTPB) {
        int i = idx >> 5, n4 = idx & 31;
        cpa16(buf + B_B + i * DN + n4 * 4, Bg + (size_t)i * (NH * DN) + n4 * 4);
    }
    // raw CB: 16B contiguous
#pragma unroll
    for (int idx = tid; idx < CS * CS / 4; idx += MTPB)
        cpa16(buf + B_CB + idx * 4, CBg + idx * 4);
    // X slice
    if (tid < CS * PW / 4) {
        int i = tid >> 2, p4 = tid & 3;
        cpa16(buf + B_X + i * PW + p4 * 4, Xg + (size_t)i * (NH * DP) + p4 * 4);
    }
    // A raw
    if (tid < CS)
        cpa4(buf + B_A + tid, A + ((size_t)((size_t)b * SEQ + cc * CS + tid)) * NH + h);
}

// ---------------- persistent sequential kernel ----------------
__global__ void __launch_bounds__(MTPB, 1) ssd_main_kernel(
    const float* __restrict__ X, const float* __restrict__ A,
    const float* __restrict__ Bm, const float* __restrict__ Cm,
    const float* __restrict__ la, const float* __restrict__ lb,
    const float* __restrict__ ema0, float* __restrict__ Y) {
    extern __shared__ float smem[];
    const int tid = threadIdx.x;
    const int lane = tid & 31;
    const int wid = tid >> 5;
    const int pair = blockIdx.x >> 2;
    const int slice = blockIdx.x & 3;
    const int b = pair >> 4, h = pair & 15;
    const int p0 = slice * PW;
    const int yi = tid & 63;            // output row
    const int pg = (tid >> 6) & 3;      // p group for Y
    const int tg = tid >> 8;            // thread-group half (0/1)
    const int n0 = tid & 127;           // state row for h-update
    const int pgh = tid >> 7;           // p group for h-update

    float* sh   = smem + OFF_SH;
    float* sM   = smem + OFF_SM;
    float* sXw  = smem + OFF_SXW;       // also reused as sPart
    float* sP   = smem + OFF_SP;
    float* sDfs = smem + OFF_DFS;
    float* sEma = smem + OFF_EMA;
    float* sAB  = smem + OFF_AB;
    float* sBet = smem + OFF_BET;
    float* sDS  = smem + OFF_DS;
    float* sRed = smem + OFF_RED;

    for (int i = tid; i < DN * PW; i += MTPB) sh[i] = 0.f;
    if (tid < NH) {
        float v = fminf(fmaxf(la[tid], -3.32f), -0.015f);
        sAB[tid] = 1.f - exp2f(v);
        float w = fminf(fmaxf(lb[tid], -2.f), 2.f);
        sBet[tid] = exp2f(w);
        sEma[tid] = ema0[tid];
    }
    prefetch_chunk(0, smem + OFF_BUF0A, b, h, pair, p0, tid, X, A, Bm, Cm);
    CP_COMMIT();
    __syncthreads();

    for (int c = 0; c < NC; ++c) {
        float* cur = smem + (((c & 1) == 0) ? OFF_BUF0A : OFF_BUF1);
        float* nxt = smem + (((c & 1) == 0) ? OFF_BUF1 : OFF_BUF0A);

        if (c + 1 < NC) {
            prefetch_chunk(c + 1, nxt, b, h, pair, p0, tid, X, A, Bm, Cm);
            CP_COMMIT();
            CP_WAIT1();
        } else {
            CP_WAIT0();
        }
        __syncthreads();

        // ---- warp-0 prefix scan of raw A (2 elems/lane) ----
        if (wid == 0) {
            const float* sA = cur + B_A;
            float v0 = sA[2 * lane], v1 = sA[2 * lane + 1];
            float s = v0 + v1;
#pragma unroll
            for (int o = 1; o < 32; o <<= 1) {
                float t = __shfl_up_sync(0xffffffffu, s, o);
                if (lane >= o) s += t;
            }
            sP[2 * lane] = s - v1;
            sP[2 * lane + 1] = s;
        }

        // ---- ds-independent Y2 = C @ h_prev (split n across tg) ----
        float4 y2 = make_float4(0.f, 0.f, 0.f, 0.f);
        if (c > 0) {
            const float* crow = cur + B_C + yi * DN;
            const int sw = yi & 31;
            const float* hcol = sh + pg * 4;
#pragma unroll
            for (int g = 0; g < 16; g++) {
                int gg = tg * 16 + g;
                float4 cv = *(const float4*)(crow + ((gg ^ sw) << 2));
                const float* hp = hcol + gg * 4 * PW;
                float4 h0 = *(const float4*)(hp);
                float4 h1 = *(const float4*)(hp + PW);
                float4 h2 = *(const float4*)(hp + 2 * PW);
                float4 h3 = *(const float4*)(hp + 3 * PW);
                y2.x = fmaf(cv.x, h0.x, y2.x); y2.y = fmaf(cv.x, h0.y, y2.y);
                y2.z = fmaf(cv.x, h0.z, y2.z); y2.w = fmaf(cv.x, h0.w, y2.w);
                y2.x = fmaf(cv.y, h1.x, y2.x); y2.y = fmaf(cv.y, h1.y, y2.y);
                y2.z = fmaf(cv.y, h1.z, y2.z); y2.w = fmaf(cv.y, h1.w, y2.w);
                y2.x = fmaf(cv.z, h2.x, y2.x); y2.y = fmaf(cv.z, h2.y, y2.y);
                y2.z = fmaf(cv.z, h2.z, y2.z); y2.w = fmaf(cv.z, h2.w, y2.w);
                y2.x = fmaf(cv.w, h3.x, y2.x); y2.y = fmaf(cv.w, h3.y, y2.y);
                y2.z = fmaf(cv.w, h3.z, y2.z); y2.w = fmaf(cv.w, h3.w, y2.w);
            }
        }

        // ---- wait for previous chunk's err, then gate ----
        if (c > 0) {
            if (tid == 0) {
                while (*(volatile unsigned*)&g_release < (unsigned)c) { }
                __threadfence();
            }
            __syncthreads();
            if (wid == 0) {
                int hh = lane & 15;
                float4 ev = __ldcg((const float4*)&g_err[(c - 1) & 1][lane][0]);
                float e = ((ev.x + ev.y) + (ev.z + ev.w)) * (1.f / (float)(DN * DP));
                float e0 = __shfl_sync(0xffffffffu, e, hh);
                float e1 = __shfl_sync(0xffffffffu, e, hh + 16);
                float emn = 0.99f * sEma[hh] + 0.01f * (0.5f * (e0 + e1));
                __syncwarp();
                if (lane < 16) sEma[hh] = emn;
                __syncwarp();
                float nrm = e / (emn + 1e-6f);
                float boost = fmaxf(tanhf(sBet[hh] * nrm), 0.f);
                float ab = sAB[hh];
                float alpha = fminf(fmaxf(ab + (1.f - ab) * boost, 0.01f), 0.999f);
                float oma = 1.f - alpha;
#pragma unroll
                for (int o = 16; o; o >>= 1) oma += __shfl_xor_sync(0xffffffffu, oma, o);
                if (lane == 0) sDS[0] = oma * (1.f / 32.f);
            }
        } else {
            if (tid == 0) sDS[0] = 1.f;
        }
        __syncthreads();

        const float dsv = sDS[0];
        const float pT = sP[CS - 1];
        if (tid < CS) sDfs[tid] = __expf(dsv * sP[tid]);
        {
            const float* sX = cur + B_X;
#pragma unroll
            for (int k = tid; k < CS * PW; k += MTPB) {
                int r = k >> 4;
                sXw[k] = __expf(dsv * (pT - sP[r])) * sX[k];
            }
        }
        __syncthreads();

        // ---- h update: h = dt*h + B^T @ (dte*X); err partial ----
        float esum;
        {
            const float* sBt = cur + B_B;
            const float* xw = sXw + pgh * 4;
            float4 c1 = make_float4(0.f, 0.f, 0.f, 0.f);
#pragma unroll 8
            for (int t = 0; t < CS; t++) {
                float b1 = sBt[t * DN + n0];
                float4 w = *(const float4*)(xw + t * PW);
                c1.x = fmaf(b1, w.x, c1.x); c1.y = fmaf(b1, w.y, c1.y);
                c1.z = fmaf(b1, w.z, c1.z); c1.w = fmaf(b1, w.w, c1.w);
            }
            float dt = __expf(dsv * pT);
            float* hp = sh + n0 * PW + pgh * 4;
            float4 hv = *(float4*)hp;
            hv.x = fmaf(dt, hv.x, c1.x); hv.y = fmaf(dt, hv.y, c1.y);
            hv.z = fmaf(dt, hv.z, c1.z); hv.w = fmaf(dt, hv.w, c1.w);
            *(float4*)hp = hv;
            esum = c1.x * c1.x + c1.y * c1.y + c1.z * c1.z + c1.w * c1.w;
        }
#pragma unroll
        for (int o = 16; o; o >>= 1) esum += __shfl_xor_sync(0xffffffffu, esum, o);
        if (lane == 0) sRed[wid] = esum;
        __syncthreads();

        // ---- publish err + EARLY arrive ----
        if (tid == 0) {
            float tot = 0.f;
#pragma unroll
            for (int w = 0; w < 16; w++) tot += sRed[w];
            g_err[c & 1][pair][slice] = tot;
            __threadfence();
            unsigned a = atomicAdd(&g_arrive, 1u);
            if (a == (unsigned)(c + 1) * (unsigned)MAIN_CTAS - 1u)
                atomicExch(&g_release, (unsigned)(c + 1));
        }

        // ---- shadow: build masked L*CB ----
        {
            const float* sCB = cur + B_CB;
#pragma unroll
            for (int idx = tid; idx < CS * CS; idx += MTPB) {
                int i = idx >> 6, j = idx & 63;
                float v = (i >= j) ? sCB[idx] * __expf(dsv * (sP[i] - sP[j])) : 0.f;
                sM[i * 65 + j] = v;
            }
        }
        __syncthreads();

        // ---- Y = sM@X (split j) + dfs*Y2, combine halves via sXw(=sPart) ----
        {
            float4 acc = make_float4(0.f, 0.f, 0.f, 0.f);
            if (!(tg == 1 && yi < 32)) {
                const float* mrow = sM + yi * 65;
                const float* xcol = cur + B_X + pg * 4;
#pragma unroll 8
                for (int j = tg * 32; j < tg * 32 + 32; j++) {
                    float m = mrow[j];
                    float4 x = *(const float4*)(xcol + j * PW);
                    acc.x = fmaf(m, x.x, acc.x);
                    acc.y = fmaf(m, x.y, acc.y);
                    acc.z = fmaf(m, x.z, acc.z);
                    acc.w = fmaf(m, x.w, acc.w);
                }
            }
            float d = sDfs[yi];
            acc.x = fmaf(d, y2.x, acc.x);
            acc.y = fmaf(d, y2.y, acc.y);
            acc.z = fmaf(d, y2.z, acc.z);
            acc.w = fmaf(d, y2.w, acc.w);
            float* sPart = sXw;
            if (tg == 1) *(float4*)(sPart + yi * PW + pg * 4) = acc;
            __syncthreads();
            if (tg == 0) {
                float4 o = *(const float4*)(sPart + yi * PW + pg * 4);
                acc.x += o.x; acc.y += o.y; acc.z += o.z; acc.w += o.w;
                size_t rowbase = ((size_t)((size_t)b * SEQ + (size_t)c * CS) * NH + h);
                float* yo = Y + (rowbase + (size_t)yi * NH) * DP + p0 + pg * 4;
                *(float4*)yo = acc;
            }
        }
        __syncthreads();  // protect cur buf + sXw before next iteration
    }
}

// ---------------- launch ----------------
extern "C" void kernel_launch(void* const* d_in, const int* in_sizes, int n_in,
                              void* d_out, int out_size) {
    const float* X  = (const float*)d_in[0];
    const float* A  = (const float*)d_in[1];
    const float* Bm = (const float*)d_in[2];
    const float* Cm = (const float*)d_in[3];
    const float* la = (const float*)d_in[4];
    const float* lb = (const float*)d_in[5];
    const float* em = (const float*)d_in[6];
    float* Y = (float*)d_out;

    const int cb_smem = 2 * CS * 129 * sizeof(float);
    const int main_smem = SMEM_FLOATS * sizeof(float);
    cudaFuncSetAttribute(cb_kernel, cudaFuncAttributeMaxDynamicSharedMemorySize, cb_smem);
    cudaFuncSetAttribute(ssd_main_kernel, cudaFuncAttributeMaxDynamicSharedMemorySize, main_smem);

    cb_kernel<<<NC * NPAIR, CTPB, cb_smem>>>(Cm, Bm);
    ssd_main_kernel<<<MAIN_CTAS, MTPB, main_smem>>>(X, A, Bm, Cm, la, lb, em, Y);
}

// round 4
// speedup vs baseline: 3.1398x; 1.3016x over previous
#include <cuda_runtime.h>

#define BSZ 2
#define SEQ 4096
#define NH 16
#define DP 64
#define DN 128
#define CS 64
#define NC 64
#define NPAIR 32
#define NSLICE 4
#define PW 16
#define P1_CTAS 128
#define TPB 512
#define CTPB 256

// ---------------- device scratch ----------------
__device__ float g_CB[(size_t)NC * NPAIR * CS * CS];        // 33.5 MB C·B^T
__device__ float g_h[(size_t)NC * NPAIR * DN * DP];         // 67 MB h_prev per chunk (p-major [p][n])
__device__ float g_ds[NC];
__device__ float g_err[2][NPAIR][NSLICE];
__device__ unsigned g_arrive;

// ---------------- cp.async helpers ----------------
__device__ __forceinline__ void cpa16(float* s, const float* g) {
    unsigned a = (unsigned)__cvta_generic_to_shared(s);
    asm volatile("cp.async.cg.shared.global [%0], [%1], 16;\n" :: "r"(a), "l"(g));
}
__device__ __forceinline__ void cpa4(float* s, const float* g) {
    unsigned a = (unsigned)__cvta_generic_to_shared(s);
    asm volatile("cp.async.ca.shared.global [%0], [%1], 4;\n" :: "r"(a), "l"(g));
}
#define CP_COMMIT() asm volatile("cp.async.commit_group;\n" ::: "memory")
#define CP_WAIT1()  asm volatile("cp.async.wait_group 1;\n" ::: "memory")
#define CP_WAIT0()  asm volatile("cp.async.wait_group 0;\n" ::: "memory")

// ---------------- pre-pass: lower-triangle CB tiles ----------------
__global__ void __launch_bounds__(CTPB) cb_kernel(const float* __restrict__ Cm,
                                                  const float* __restrict__ Bm) {
    if (blockIdx.x == 0 && threadIdx.x == 0) { g_arrive = 0u; }
    extern __shared__ float smem[];
    float* sC = smem;                // [64][129]
    float* sBt = smem + CS * 129;    // [64][129]
    int tile = blockIdx.x;
    int c = tile >> 5;
    int pair = tile & 31;
    int b = pair >> 4, h = pair & 15;
    size_t base = ((size_t)((size_t)b * SEQ + (size_t)c * CS) * NH + h) * DN;
    const float* Cg = Cm + base;
    const float* Bg = Bm + base;
    const int gs = NH * DN;
    for (int idx = threadIdx.x; idx < CS * DN; idx += CTPB) {
        int i = idx >> 7, n = idx & 127;
        sC[i * 129 + n] = Cg[(size_t)i * gs + n];
        sBt[i * 129 + n] = Bg[(size_t)i * gs + n];
    }
    __syncthreads();
    int t = threadIdx.x;
    if (t < 136) {
        int ti = (int)((sqrtf(8.f * (float)t + 1.f) - 1.f) * 0.5f);
        while ((ti + 1) * (ti + 2) / 2 <= t) ti++;
        while (ti * (ti + 1) / 2 > t) ti--;
        int tj = t - ti * (ti + 1) / 2;
        int i0 = ti * 4, j0 = tj * 4;
        float acc[4][4];
#pragma unroll
        for (int a = 0; a < 4; a++)
#pragma unroll
            for (int e = 0; e < 4; e++) acc[a][e] = 0.f;
#pragma unroll 4
        for (int n = 0; n < DN; n++) {
            float cr[4], br[4];
#pragma unroll
            for (int a = 0; a < 4; a++) cr[a] = sC[(i0 + a) * 129 + n];
#pragma unroll
            for (int e = 0; e < 4; e++) br[e] = sBt[(j0 + e) * 129 + n];
#pragma unroll
            for (int a = 0; a < 4; a++)
#pragma unroll
                for (int e = 0; e < 4; e++) acc[a][e] = fmaf(cr[a], br[e], acc[a][e]);
        }
        float* out = g_CB + (size_t)(c * NPAIR + pair) * CS * CS;
#pragma unroll
        for (int a = 0; a < 4; a++) {
            float4 v = make_float4(acc[a][0], acc[a][1], acc[a][2], acc[a][3]);
            *reinterpret_cast<float4*>(out + (i0 + a) * CS + j0) = v;
        }
    }
}

// ============================================================================
// PASS 1: sequential gate + h recurrence (h in registers), err, ds, h_prev out
// ============================================================================
#define O1_XW   0        // dte*X [64][16]   1024
#define O1_P    1024     // 64
#define O1_EMA  1088     // 16
#define O1_AB   1104     // 16
#define O1_BET  1120     // 16
#define O1_DS   1136     // 1
#define O1_RED  1140     // 16
#define O1_BUF0 1160
#define B1_B 0           // B tile [64][128] 8192
#define B1_X 8192        // X slice [64][16] 1024
#define B1_A 9216        // 64
#define BUF1SZ 9280
#define O1_BUF1 (O1_BUF0 + BUF1SZ)
#define SMEM1_FLOATS (O1_BUF1 + BUF1SZ)   // 19720 floats = 78880 B

__device__ __forceinline__ void p1_prefetch(
    int cc, float* buf, int b, int h, int p0, int tid,
    const float* __restrict__ X, const float* __restrict__ A,
    const float* __restrict__ Bm) {
    size_t rowbase = ((size_t)((size_t)b * SEQ + (size_t)cc * CS) * NH + h);
    const float* Bg = Bm + rowbase * DN;
    const float* Xg = X + rowbase * DP + p0;
#pragma unroll
    for (int idx = tid; idx < CS * DN / 4; idx += TPB) {
        int i = idx >> 5, n4 = idx & 31;
        cpa16(buf + B1_B + i * DN + n4 * 4, Bg + (size_t)i * (NH * DN) + n4 * 4);
    }
    if (tid < CS * PW / 4) {
        int i = tid >> 2, p4 = tid & 3;
        cpa16(buf + B1_X + i * PW + p4 * 4, Xg + (size_t)i * (NH * DP) + p4 * 4);
    }
    if (tid < CS)
        cpa4(buf + B1_A + tid, A + ((size_t)((size_t)b * SEQ + cc * CS + tid)) * NH + h);
}

__global__ void __launch_bounds__(TPB, 1) pass1_kernel(
    const float* __restrict__ X, const float* __restrict__ A,
    const float* __restrict__ Bm,
    const float* __restrict__ la, const float* __restrict__ lb,
    const float* __restrict__ ema0) {
    extern __shared__ float smem[];
    const int tid = threadIdx.x;
    const int lane = tid & 31;
    const int wid = tid >> 5;
    const int pair = blockIdx.x >> 2;
    const int slice = blockIdx.x & 3;
    const int b = pair >> 4, h = pair & 15;
    const int p0 = slice * PW;
    const int n0 = tid & 127;
    const int pl = (tid >> 7) * 4;    // p offset within slice (0,4,8,12)

    float* sXw  = smem + O1_XW;
    float* sP   = smem + O1_P;
    float* sEma = smem + O1_EMA;
    float* sAB  = smem + O1_AB;
    float* sBet = smem + O1_BET;
    float* sDS  = smem + O1_DS;
    float* sRed = smem + O1_RED;

    if (tid < NH) {
        float v = fminf(fmaxf(la[tid], -3.32f), -0.015f);
        sAB[tid] = 1.f - exp2f(v);
        float w = fminf(fmaxf(lb[tid], -2.f), 2.f);
        sBet[tid] = exp2f(w);
        sEma[tid] = ema0[tid];
    }
    float4 hreg = make_float4(0.f, 0.f, 0.f, 0.f);

    p1_prefetch(0, smem + O1_BUF0, b, h, p0, tid, X, A, Bm);
    CP_COMMIT();
    __syncthreads();

    for (int c = 0; c < NC; ++c) {
        float* cur = smem + (((c & 1) == 0) ? O1_BUF0 : O1_BUF1);
        float* nxt = smem + (((c & 1) == 0) ? O1_BUF1 : O1_BUF0);
        if (c + 1 < NC) {
            p1_prefetch(c + 1, nxt, b, h, p0, tid, X, A, Bm);
            CP_COMMIT();
            CP_WAIT1();
        } else {
            CP_WAIT0();
        }
        __syncthreads();

        // prefix scan of A (warp 0)
        if (wid == 0) {
            const float* sA = cur + B1_A;
            float v0 = sA[2 * lane], v1 = sA[2 * lane + 1];
            float s = v0 + v1;
#pragma unroll
            for (int o = 1; o < 32; o <<= 1) {
                float t = __shfl_up_sync(0xffffffffu, s, o);
                if (lane >= o) s += t;
            }
            sP[2 * lane] = s - v1;
            sP[2 * lane + 1] = s;
        }

        // gate
        if (c > 0) {
            if (tid == 0) {
                unsigned v;
                unsigned target = (unsigned)c * (unsigned)P1_CTAS;
                do {
                    asm volatile("ld.acquire.gpu.global.u32 %0, [%1];"
                                 : "=r"(v) : "l"(&g_arrive) : "memory");
                } while (v < target);
            }
            __syncthreads();
            if (wid == 0) {
                int hh = lane & 15;
                float4 ev = __ldcg((const float4*)&g_err[(c - 1) & 1][lane][0]);
                float e = ((ev.x + ev.y) + (ev.z + ev.w)) * (1.f / (float)(DN * DP));
                float e0 = __shfl_sync(0xffffffffu, e, hh);
                float e1 = __shfl_sync(0xffffffffu, e, hh + 16);
                float emn = 0.99f * sEma[hh] + 0.01f * (0.5f * (e0 + e1));
                __syncwarp();
                if (lane < 16) sEma[hh] = emn;
                __syncwarp();
                float nrm = e / (emn + 1e-6f);
                float boost = fmaxf(tanhf(sBet[hh] * nrm), 0.f);
                float ab = sAB[hh];
                float alpha = fminf(fmaxf(ab + (1.f - ab) * boost, 0.01f), 0.999f);
                float oma = 1.f - alpha;
#pragma unroll
                for (int o = 16; o; o >>= 1) oma += __shfl_xor_sync(0xffffffffu, oma, o);
                if (lane == 0) sDS[0] = oma * (1.f / 32.f);
            }
        } else {
            if (tid == 0) sDS[0] = 1.f;
        }
        __syncthreads();

        const float dsv = sDS[0];
        const float pT = sP[CS - 1];
        // dte-weighted X
        {
            const float* sX = cur + B1_X;
#pragma unroll
            for (int k = tid; k < CS * PW; k += TPB) {
                int r = k >> 4;
                sXw[k] = __expf(dsv * (pT - sP[r])) * sX[k];
            }
        }
        __syncthreads();

        // h update: h = dt*h + B^T @ (dte*X)
        float esum;
        {
            const float* sBt = cur + B1_B;
            const float* xw = sXw + pl;
            float4 c1 = make_float4(0.f, 0.f, 0.f, 0.f);
#pragma unroll 8
            for (int t = 0; t < CS; t++) {
                float b1 = sBt[t * DN + n0];
                float4 w = *(const float4*)(xw + t * PW);
                c1.x = fmaf(b1, w.x, c1.x); c1.y = fmaf(b1, w.y, c1.y);
                c1.z = fmaf(b1, w.z, c1.z); c1.w = fmaf(b1, w.w, c1.w);
            }
            float dt = __expf(dsv * pT);
            hreg.x = fmaf(dt, hreg.x, c1.x);
            hreg.y = fmaf(dt, hreg.y, c1.y);
            hreg.z = fmaf(dt, hreg.z, c1.z);
            hreg.w = fmaf(dt, hreg.w, c1.w);
            esum = c1.x * c1.x + c1.y * c1.y + c1.z * c1.z + c1.w * c1.w;
        }
        // store h_prev for chunk c+1 (p-major)
        if (c + 1 < NC) {
            float* gh = g_h + ((size_t)(c + 1) * NPAIR + pair) * (DN * DP)
                        + (size_t)(p0 + pl) * DN + n0;
            gh[0]       = hreg.x;
            gh[DN]      = hreg.y;
            gh[2 * DN]  = hreg.z;
            gh[3 * DN]  = hreg.w;
        }
#pragma unroll
        for (int o = 16; o; o >>= 1) esum += __shfl_xor_sync(0xffffffffu, esum, o);
        if (lane == 0) sRed[wid] = esum;
        __syncthreads();
        if (tid == 0) {
            float tot = 0.f;
#pragma unroll
            for (int w = 0; w < 16; w++) tot += sRed[w];
            asm volatile("st.global.cg.f32 [%0], %1;"
                         :: "l"(&g_err[c & 1][pair][slice]), "f"(tot) : "memory");
            unsigned d_;
            asm volatile("atom.release.gpu.global.add.u32 %0, [%1], 1;"
                         : "=r"(d_) : "l"(&g_arrive) : "memory");
        }
        if (blockIdx.x == 0 && tid == 32) g_ds[c] = dsv;
    }
}

// ============================================================================
// PASS 2: fully parallel output  Y = dfs_i * ( (CBm @ Xs) + C @ h_prev )
// ============================================================================
#define P2_C   0        // C [64][128] swizzled  8192
#define P2_H   8192     // h_prev p-major [64][128]  8192
#define P2_CB  16384    // CB [64][64] swizzled  4096
#define P2_X   20480    // Xs [64][64]           4096
#define P2_A   24576    // 64
#define P2_P   24640    // 64
#define P2_DFS 24704    // 64
#define P2_INV 24768    // 64
#define SMEM2_FLOATS 24832   // 99328 B

__global__ void __launch_bounds__(TPB, 2) pass2_kernel(
    const float* __restrict__ X, const float* __restrict__ A,
    const float* __restrict__ Cm, float* __restrict__ Y) {
    extern __shared__ float smem[];
    const int tid = threadIdx.x;
    const int lane = tid & 31;
    const int wid = tid >> 5;
    const int c = blockIdx.x >> 5;
    const int pair = blockIdx.x & 31;
    const int b = pair >> 4, h = pair & 15;
    const int yi = tid & 63;
    const int pq = tid >> 6;     // 8 p-groups of 8

    float* sC   = smem + P2_C;
    float* sH   = smem + P2_H;
    float* sCB  = smem + P2_CB;
    float* sX   = smem + P2_X;
    float* sP   = smem + P2_P;
    float* sDfs = smem + P2_DFS;
    float* sInv = smem + P2_INV;

    const size_t rowbase = ((size_t)((size_t)b * SEQ + (size_t)c * CS) * NH + h);
    const float* Cg = Cm + rowbase * DN;
    const float* Xg = X + rowbase * DP;
    const float* CBg = g_CB + (size_t)(c * NPAIR + pair) * CS * CS;
    const float* Hg = g_h + ((size_t)c * NPAIR + pair) * (DN * DP);

    // ---- async loads ----
#pragma unroll
    for (int idx = tid; idx < CS * DN / 4; idx += TPB) {
        int i = idx >> 5, g = idx & 31;
        cpa16(sC + i * DN + ((g ^ (i & 31)) << 2), Cg + (size_t)i * (NH * DN) + g * 4);
    }
    if (c > 0) {
#pragma unroll
        for (int idx = tid; idx < DN * DP / 4; idx += TPB)
            cpa16(sH + idx * 4, Hg + idx * 4);
    }
#pragma unroll
    for (int idx = tid; idx < CS * CS / 4; idx += TPB) {
        int i = idx >> 4, g4 = idx & 15;
        cpa16(sCB + i * CS + ((g4 ^ (i & 15)) << 2), CBg + i * CS + g4 * 4);
    }
#pragma unroll
    for (int idx = tid; idx < CS * DP / 4; idx += TPB) {
        int j = idx >> 4, p4 = idx & 15;
        cpa16(sX + j * DP + p4 * 4, Xg + (size_t)j * (NH * DP) + p4 * 4);
    }
    if (tid < CS)
        cpa4(smem + P2_A + tid, A + ((size_t)((size_t)b * SEQ + c * CS + tid)) * NH + h);
    CP_COMMIT();
    CP_WAIT0();
    __syncthreads();

    // ---- prefix scan of A ----
    if (wid == 0) {
        const float* sA = smem + P2_A;
        float v0 = sA[2 * lane], v1 = sA[2 * lane + 1];
        float s = v0 + v1;
#pragma unroll
        for (int o = 1; o < 32; o <<= 1) {
            float t = __shfl_up_sync(0xffffffffu, s, o);
            if (lane >= o) s += t;
        }
        sP[2 * lane] = s - v1;
        sP[2 * lane + 1] = s;
    }
    __syncthreads();

    const float dsv = (c == 0) ? 1.f : __ldg(&g_ds[c]);
    if (tid < CS) {
        float a = dsv * sP[tid];
        sDfs[tid] = __expf(a);
        sInv[tid] = __expf(-a);
    }
    __syncthreads();

    // scale X rows by inv_j; zero upper triangle of CB (swizzled addressing)
#pragma unroll
    for (int idx = tid; idx < CS * DP; idx += TPB)
        sX[idx] *= sInv[idx >> 6];
#pragma unroll
    for (int idx = tid; idx < CS * CS; idx += TPB) {
        int i = idx >> 6, j = idx & 63;
        if (j > i)
            sCB[i * CS + (((j >> 2) ^ (i & 15)) << 2) + (j & 3)] = 0.f;
    }
    __syncthreads();

    // ---- GEMMs ----
    float acc[8];
#pragma unroll
    for (int e = 0; e < 8; e++) acc[e] = 0.f;

    if (c > 0) {
        const float* crow = sC + yi * DN;
        const int sw = yi & 31;
        const float* hb = sH + pq * 8 * DN;
#pragma unroll 4
        for (int g = 0; g < 32; g++) {
            float4 cv = *(const float4*)(crow + ((g ^ sw) << 2));
#pragma unroll
            for (int e = 0; e < 8; e++) {
                float4 hv = *(const float4*)(hb + e * DN + g * 4);
                acc[e] = fmaf(cv.x, hv.x, acc[e]);
                acc[e] = fmaf(cv.y, hv.y, acc[e]);
                acc[e] = fmaf(cv.z, hv.z, acc[e]);
                acc[e] = fmaf(cv.w, hv.w, acc[e]);
            }
        }
    }
    {
        const float* cbrow = sCB + yi * CS;
        const int sw4 = yi & 15;
        const int gmax = (yi < 32) ? 8 : 16;   // warp-uniform triangular skip
        for (int g4 = 0; g4 < gmax; g4++) {
            float4 cb = *(const float4*)(cbrow + ((g4 ^ sw4) << 2));
#pragma unroll
            for (int k = 0; k < 4; k++) {
                float cbk = (k == 0) ? cb.x : (k == 1) ? cb.y : (k == 2) ? cb.z : cb.w;
                const float* xr = sX + (g4 * 4 + k) * DP + pq * 8;
                float4 x0 = *(const float4*)(xr);
                float4 x1 = *(const float4*)(xr + 4);
                acc[0] = fmaf(cbk, x0.x, acc[0]);
                acc[1] = fmaf(cbk, x0.y, acc[1]);
                acc[2] = fmaf(cbk, x0.z, acc[2]);
                acc[3] = fmaf(cbk, x0.w, acc[3]);
                acc[4] = fmaf(cbk, x1.x, acc[4]);
                acc[5] = fmaf(cbk, x1.y, acc[5]);
                acc[6] = fmaf(cbk, x1.z, acc[6]);
                acc[7] = fmaf(cbk, x1.w, acc[7]);
            }
        }
    }
    // ---- scale + store ----
    {
        float d = sDfs[yi];
        float* yo = Y + (rowbase + (size_t)yi * NH) * DP + pq * 8;
        float4 o0 = make_float4(acc[0] * d, acc[1] * d, acc[2] * d, acc[3] * d);
        float4 o1 = make_float4(acc[4] * d, acc[5] * d, acc[6] * d, acc[7] * d);
        *(float4*)yo = o0;
        *(float4*)(yo + 4) = o1;
    }
}

// ---------------- launch ----------------
extern "C" void kernel_launch(void* const* d_in, const int* in_sizes, int n_in,
                              void* d_out, int out_size) {
    const float* X  = (const float*)d_in[0];
    const float* A  = (const float*)d_in[1];
    const float* Bm = (const float*)d_in[2];
    const float* Cm = (const float*)d_in[3];
    const float* la = (const float*)d_in[4];
    const float* lb = (const float*)d_in[5];
    const float* em = (const float*)d_in[6];
    float* Y = (float*)d_out;

    const int cb_smem = 2 * CS * 129 * sizeof(float);
    const int p1_smem = SMEM1_FLOATS * sizeof(float);
    const int p2_smem = SMEM2_FLOATS * sizeof(float);
    cudaFuncSetAttribute(cb_kernel, cudaFuncAttributeMaxDynamicSharedMemorySize, cb_smem);
    cudaFuncSetAttribute(pass1_kernel, cudaFuncAttributeMaxDynamicSharedMemorySize, p1_smem);
    cudaFuncSetAttribute(pass2_kernel, cudaFuncAttributeMaxDynamicSharedMemorySize, p2_smem);

    cb_kernel<<<NC * NPAIR, CTPB, cb_smem>>>(Cm, Bm);
    pass1_kernel<<<P1_CTAS, TPB, p1_smem>>>(X, A, Bm, la, lb, em);
    pass2_kernel<<<NC * NPAIR, TPB, p2_smem>>>(X, A, Cm, Y);
}